// round 3
// baseline (speedup 1.0000x reference)
#include <cuda_runtime.h>
#include <stdint.h>

// GLCMAttention, round 3 (= round-2 design, compile fix):
// qbuf eliminated (shfl neighbor pipeline), uint8 per-thread histograms
// (64KB) with mid-point flush -> 3 CTAs/SM.
//
// hist layout (conflict-free, bank == lane for every access):
//   byte addr = tg*8192 + (q*8+qs)*128 + lane*4 + angle
// counter id k = (q*8+qs)*4 + angle, k in 0..255; thread t reduces counter t.

#define HIST_BYTES 65536
#define SMEM_TOTAL (HIST_BYTES + 256*4 + 16*4 + 16)

// Thread t sums counter-id t across all 256 per-thread regions.
__device__ __forceinline__ unsigned flush_hist(const unsigned char* hist,
                                               int t, int lane)
{
    unsigned acc = 0;
    unsigned pairoff = ((unsigned)(t >> 2) << 7) + (unsigned)(t & 3);
    #pragma unroll
    for (int tg2 = 0; tg2 < 8; ++tg2) {
        unsigned rb = (unsigned)tg2 << 13;
        #pragma unroll
        for (int l = 0; l < 32; ++l) {
            unsigned lw = (unsigned)((l + lane) & 31);   // stagger banks
            acc += hist[rb + pairoff + (lw << 2)];
        }
    }
    return acc;
}

__global__ void __launch_bounds__(256, 3)
glcm_attn_kernel(const float* __restrict__ x,
                 const float* __restrict__ W1,
                 const float* __restrict__ W2,
                 float* __restrict__ out)
{
    extern __shared__ unsigned char smem[];
    unsigned char* hist   = smem;
    unsigned int*  totals = (unsigned int*)(smem + HIST_BYTES);
    float*         feats  = (float*)(totals + 256);
    float*         scalep = feats + 16;

    const int t    = threadIdx.x;
    const int lane = t & 31;
    const int bc   = blockIdx.x;
    const float* xp = x   + (size_t)bc * 65536;
    float*       op = out + (size_t)bc * 65536;

    // ---- zero hist (64KB = 4096 uint4, conflict-free) ----
    uint4* h4 = (uint4*)hist;
    #pragma unroll
    for (int i = 0; i < 16; ++i) h4[t + (i << 8)] = make_uint4(0u, 0u, 0u, 0u);
    __syncthreads();

    unsigned char* hb = hist + ((t >> 5) << 13) + (lane << 2);
    unsigned acc = 0;

    // ---- prologue: row 0 ----
    unsigned qc = (unsigned)(int)(xp[t] * 7.0f);
    unsigned ql = __shfl_up_sync(0xFFFFFFFFu, qc, 1);
    if (lane == 0) ql = (t == 0) ? 0u : (unsigned)(int)(xp[t - 1] * 7.0f);

    const float* rowp = xp + 256;

    // One row step: load row y+1 (if LOADNEXT), bump 4 counters for row y.
#define ROWSTEP(LOADNEXT)                                                     \
    {                                                                         \
        unsigned nc, nl, nr;                                                  \
        if (LOADNEXT) {                                                       \
            float w = rowp[t];                                                \
            nc = (unsigned)(int)(w * 7.0f);                                   \
            nl = __shfl_up_sync(0xFFFFFFFFu, nc, 1);                          \
            if (lane == 0)                                                    \
                nl = (t == 0) ? 0u : (unsigned)(int)(rowp[t - 1] * 7.0f);     \
            nr = __shfl_down_sync(0xFFFFFFFFu, nc, 1);                        \
            if (lane == 31)                                                   \
                nr = (t == 255) ? 0u : (unsigned)(int)(rowp[t + 1] * 7.0f);   \
            rowp += 256;                                                      \
        } else { nc = 0u; nl = 0u; nr = 0u; }                                 \
        unsigned char* b0 = hb + (qc << 10);                                  \
        b0[(ql << 7) + 0] = (unsigned char)(b0[(ql << 7) + 0] + 1u);          \
        b0[(nl << 7) + 1] = (unsigned char)(b0[(nl << 7) + 1] + 1u);          \
        b0[(nc << 7) + 2] = (unsigned char)(b0[(nc << 7) + 2] + 1u);          \
        b0[(nr << 7) + 3] = (unsigned char)(b0[(nr << 7) + 3] + 1u);          \
        qc = nc; ql = nl;                                                     \
    }

    // ---- phase 1: rows 0..127 (max count per u8 counter = 128, safe) ----
    #pragma unroll 4
    for (int y = 0; y < 128; ++y) ROWSTEP(1)

    // flush 1 + re-zero
    __syncthreads();
    acc += flush_hist(hist, t, lane);
    __syncthreads();
    #pragma unroll
    for (int i = 0; i < 16; ++i) h4[t + (i << 8)] = make_uint4(0u, 0u, 0u, 0u);
    __syncthreads();

    // ---- phase 2: rows 128..255 (last row pairs with zero-pad) ----
    #pragma unroll 4
    for (int y = 128; y < 255; ++y) ROWSTEP(1)
    ROWSTEP(0)

    // flush 2
    __syncthreads();
    acc += flush_hist(hist, t, lane);

    totals[t] = acc;
    __syncthreads();

    // ---- features: warp 0, lane l -> angle = l>>3, row i = l&7 ----
    if (t < 32) {
        int angle = t >> 3;
        int sub   = t & 7;
        const float inv = 1.0f / 65536.0f;
        float fi = (float)sub;
        float contrast = 0.f, homog = 0.f, energy = 0.f, corr = 0.f;
        #pragma unroll
        for (int j = 0; j < 8; ++j) {
            float p = (float)totals[(((sub << 3) + j) << 2) + angle] * inv;
            float d = fi - (float)j;
            contrast += d * d * p;
            homog    += p / (1.0f + fabsf(d));
            energy   += p * p;
            corr     += (fi - 3.5f) * ((float)j - 3.5f) * p;
        }
        #pragma unroll
        for (int off = 4; off; off >>= 1) {
            contrast += __shfl_down_sync(0xFFFFFFFFu, contrast, off);
            homog    += __shfl_down_sync(0xFFFFFFFFu, homog,    off);
            energy   += __shfl_down_sync(0xFFFFFFFFu, energy,   off);
            corr     += __shfl_down_sync(0xFFFFFFFFu, corr,     off);
        }
        if (sub == 0) {
            feats[angle * 4 + 0] = contrast;
            feats[angle * 4 + 1] = homog;
            feats[angle * 4 + 2] = energy;
            feats[angle * 4 + 3] = corr * (1.0f / 6.000001f);  // / (std^2 + 1e-6)
        }
    }
    __syncthreads();

    // ---- MLP diagonal ----
    if (t < 16) {
        float h = 0.f;
        #pragma unroll
        for (int f = 0; f < 16; ++f) h += feats[f] * W1[f * 16 + t];
        h = fmaxf(h, 0.0f);
        int c = bc & 63;
        float v = h * W2[t * 64 + c];
        #pragma unroll
        for (int off = 8; off; off >>= 1)
            v += __shfl_down_sync(0x0000FFFFu, v, off);
        if (t == 0) {
            float s = 1.0f / (1.0f + expf(-v));
            *scalep = 1.0f + s;
        }
    }
    __syncthreads();

    // ---- output: out = x * scale (x re-read, L2-hot) ----
    const float s = *scalep;
    #pragma unroll 4
    for (int k = 0; k < 64; ++k) {
        int i = t + (k << 8);
        float4 v = ((const float4*)xp)[i];
        v.x *= s; v.y *= s; v.z *= s; v.w *= s;
        ((float4*)op)[i] = v;
    }
#undef ROWSTEP
}

extern "C" void kernel_launch(void* const* d_in, const int* in_sizes, int n_in,
                              void* d_out, int out_size)
{
    (void)in_sizes; (void)n_in; (void)out_size;
    const float* x  = (const float*)d_in[0];
    const float* W1 = (const float*)d_in[1];
    const float* W2 = (const float*)d_in[2];
    float* out = (float*)d_out;

    cudaFuncSetAttribute(glcm_attn_kernel,
                         cudaFuncAttributeMaxDynamicSharedMemorySize, SMEM_TOTAL);
    glcm_attn_kernel<<<512, 256, SMEM_TOTAL>>>(x, W1, W2, out);
}

// round 4
// speedup vs baseline: 1.9413x; 1.9413x over previous
#include <cuda_runtime.h>
#include <stdint.h>

// GLCMAttention round 4: 4 pixels/thread (LDG.128 per row), u8 per-thread
// histograms (64KB, 3 CTAs/SM), per-pixel grouped RMW, dp4a flush.
//
// hist layout (bank == owner-lane for every access):
//   byte addr = tg*8192 + (q*8+qs)*128 + lane*4 + angle
// counter id k = (q*8+qs)*4 + angle; thread t reduces counter t.

#define HIST_BYTES 65536
#define SMEM_TOTAL (HIST_BYTES + 256*4 + 16*4 + 16)

__device__ __forceinline__ unsigned q7(float v) { return (unsigned)(int)(v * 7.0f); }

// Thread t sums counter-id t across all 256 per-thread regions (dp4a).
__device__ __forceinline__ unsigned flush_hist(const unsigned* histw, int t, int lane)
{
    unsigned acc = 0;
    unsigned sel = 1u << ((t & 3) * 8);          // extract byte 'angle'
    unsigned pw  = (unsigned)(t >> 2) * 32u;     // pair*128B = 32 words
    #pragma unroll
    for (int tg2 = 0; tg2 < 8; ++tg2) {
        unsigned base = (unsigned)tg2 * 2048u + pw;
        #pragma unroll
        for (int l = 0; l < 32; ++l) {
            unsigned lw = (unsigned)((l + lane) & 31);   // stagger banks
            acc = __dp4a(histw[base + lw], sel, acc);
        }
    }
    return acc;
}

// One pixel's 4 angle-counter increments: 4 distinct bytes (angle offset),
// loads grouped before stores for latency overlap.
#define PIXEL(QV, A0, A1, A2, A3)                                            \
    {                                                                        \
        unsigned char* b = hb + ((QV) << 10);                                \
        unsigned char* pa = b + ((A0) << 7);                                 \
        unsigned char* pb = b + ((A1) << 7) + 1;                             \
        unsigned char* pc = b + ((A2) << 7) + 2;                             \
        unsigned char* pd = b + ((A3) << 7) + 3;                             \
        unsigned va = *pa, vb = *pb, vc = *pc, vd = *pd;                     \
        *pa = (unsigned char)(va + 1u);                                      \
        *pb = (unsigned char)(vb + 1u);                                      \
        *pc = (unsigned char)(vc + 1u);                                      \
        *pd = (unsigned char)(vd + 1u);                                      \
    }

// Process row y (state q0..q3, cl) using next row y+1 (loaded if VALID).
#define ROWBODY(Y, VALID)                                                    \
    {                                                                        \
        float4 nv = make_float4(0.f, 0.f, 0.f, 0.f);                         \
        float nlv = 0.f, nrv = 0.f;                                          \
        if (VALID) {                                                         \
            const float* nb = rb0 + ((Y) + 1) * 256;                         \
            nv = *(const float4*)nb;                                         \
            if (lane == 0 && g != 0)   nlv = nb[-1];                         \
            if (lane == 31 && g != 63) nrv = nb[4];                          \
        }                                                                    \
        unsigned n0 = q7(nv.x), n1 = q7(nv.y), n2 = q7(nv.z), n3 = q7(nv.w); \
        unsigned nl = __shfl_up_sync(0xFFFFFFFFu, n3, 1);                    \
        if (lane == 0)  nl = q7(nlv);                                        \
        unsigned nr = __shfl_down_sync(0xFFFFFFFFu, n0, 1);                  \
        if (lane == 31) nr = q7(nrv);                                        \
        PIXEL(q0, cl, nl, n0, n1)                                            \
        PIXEL(q1, q0, n0, n1, n2)                                            \
        PIXEL(q2, q1, n1, n2, n3)                                            \
        PIXEL(q3, q2, n2, n3, nr)                                            \
        q0 = n0; q1 = n1; q2 = n2; q3 = n3; cl = nl;                         \
    }

__global__ void __launch_bounds__(256, 3)
glcm_attn_kernel(const float* __restrict__ x,
                 const float* __restrict__ W1,
                 const float* __restrict__ W2,
                 float* __restrict__ out)
{
    extern __shared__ unsigned char smem[];
    unsigned char* hist   = smem;
    unsigned*      histw  = (unsigned*)smem;
    unsigned*      totals = (unsigned*)(smem + HIST_BYTES);
    float*         feats  = (float*)(totals + 256);
    float*         scalep = feats + 16;

    const int t = threadIdx.x, lane = t & 31;
    const int bc = blockIdx.x;
    const float* xp = x   + (size_t)bc * 65536;
    float*       op = out + (size_t)bc * 65536;

    // ---- zero hist ----
    uint4* h4 = (uint4*)hist;
    #pragma unroll
    for (int i = 0; i < 16; ++i) h4[t + (i << 8)] = make_uint4(0u, 0u, 0u, 0u);
    __syncthreads();

    unsigned char* hb = hist + ((t >> 5) << 13) + (lane << 2);

    // thread -> (row strip, 4-col group)
    const int strip = t >> 6;            // rows [strip*64, strip*64+64)
    const int g     = t & 63;            // cols [g*4, g*4+4)
    const float* rb0 = xp + strip * 64 * 256 + g * 4;

    // ---- prologue: row 0 of strip ----
    float4 cv = *(const float4*)rb0;
    unsigned q0 = q7(cv.x), q1 = q7(cv.y), q2 = q7(cv.z), q3 = q7(cv.w);
    unsigned cl = __shfl_up_sync(0xFFFFFFFFu, q3, 1);
    if (lane == 0) {
        cl = 0u;
        if (g != 0) cl = q7(rb0[-1]);
    }
    unsigned acc = 0;

    // ---- phase 1: local rows 0..31 (max 128/counter) ----
    #pragma unroll 4
    for (int y = 0; y < 32; ++y) ROWBODY(y, true)

    __syncthreads();
    acc += flush_hist(histw, t, lane);
    __syncthreads();
    #pragma unroll
    for (int i = 0; i < 16; ++i) h4[t + (i << 8)] = make_uint4(0u, 0u, 0u, 0u);
    __syncthreads();

    // ---- phase 2: local rows 32..63 ----
    #pragma unroll 4
    for (int y = 32; y < 63; ++y) ROWBODY(y, true)
    ROWBODY(63, (strip < 3))             // last strip pairs with zero pad

    __syncthreads();
    acc += flush_hist(histw, t, lane);
    totals[t] = acc;
    __syncthreads();

    // ---- features: warp 0, lane l -> angle = l>>3, row i = l&7 ----
    if (t < 32) {
        int angle = t >> 3;
        int sub   = t & 7;
        const float inv = 1.0f / 65536.0f;
        float fi = (float)sub;
        float contrast = 0.f, homog = 0.f, energy = 0.f, corr = 0.f;
        #pragma unroll
        for (int j = 0; j < 8; ++j) {
            float p = (float)totals[(((sub << 3) + j) << 2) + angle] * inv;
            float d = fi - (float)j;
            contrast += d * d * p;
            homog    += p / (1.0f + fabsf(d));
            energy   += p * p;
            corr     += (fi - 3.5f) * ((float)j - 3.5f) * p;
        }
        #pragma unroll
        for (int off = 4; off; off >>= 1) {
            contrast += __shfl_down_sync(0xFFFFFFFFu, contrast, off);
            homog    += __shfl_down_sync(0xFFFFFFFFu, homog,    off);
            energy   += __shfl_down_sync(0xFFFFFFFFu, energy,   off);
            corr     += __shfl_down_sync(0xFFFFFFFFu, corr,     off);
        }
        if (sub == 0) {
            feats[angle * 4 + 0] = contrast;
            feats[angle * 4 + 1] = homog;
            feats[angle * 4 + 2] = energy;
            feats[angle * 4 + 3] = corr * (1.0f / 6.000001f);  // / (std^2+1e-6)
        }
    }
    __syncthreads();

    // ---- MLP diagonal ----
    if (t < 16) {
        float h = 0.f;
        #pragma unroll
        for (int f = 0; f < 16; ++f) h += feats[f] * W1[f * 16 + t];
        h = fmaxf(h, 0.0f);
        int c = bc & 63;
        float v = h * W2[t * 64 + c];
        #pragma unroll
        for (int off = 8; off; off >>= 1)
            v += __shfl_down_sync(0x0000FFFFu, v, off);
        if (t == 0) {
            float s = 1.0f / (1.0f + expf(-v));
            *scalep = 1.0f + s;
        }
    }
    __syncthreads();

    // ---- output: out = x * scale (x re-read, L2-hot) ----
    const float s = *scalep;
    #pragma unroll 4
    for (int k = 0; k < 64; ++k) {
        int i = t + (k << 8);
        float4 v = ((const float4*)xp)[i];
        v.x *= s; v.y *= s; v.z *= s; v.w *= s;
        ((float4*)op)[i] = v;
    }
}

extern "C" void kernel_launch(void* const* d_in, const int* in_sizes, int n_in,
                              void* d_out, int out_size)
{
    (void)in_sizes; (void)n_in; (void)out_size;
    const float* x  = (const float*)d_in[0];
    const float* W1 = (const float*)d_in[1];
    const float* W2 = (const float*)d_in[2];
    float* out = (float*)d_out;

    cudaFuncSetAttribute(glcm_attn_kernel,
                         cudaFuncAttributeMaxDynamicSharedMemorySize, SMEM_TOTAL);
    glcm_attn_kernel<<<512, 256, SMEM_TOTAL>>>(x, W1, W2, out);
}